// round 15
// baseline (speedup 1.0000x reference)
#include <cuda_runtime.h>
#include <cuda_bf16.h>
#include <cstdint>

#define NN 20000
#define DD 256
#define EE 320000
#define ET 340000   // EE + NN self loops

// ---------------- device scratch (no allocations allowed) ----------------
__device__ float g_xl[NN * DD];
__device__ float g_xr[NN * DD];
__device__ float g_h[NN * DD];          // activations (tf32-rounded fp32)
__device__ float g_wt[8 * DD * DD];     // W^T tf32-rounded, [layer*2+which][n][k]
__device__ int   g_off[NN + 1];
__device__ int   g_cur[NN];
__device__ int   g_srcs[ET];

__device__ __forceinline__ uint32_t smem_u32(const void* p) {
    uint32_t a;
    asm("{ .reg .u64 t; cvta.to.shared.u64 t, %1; cvt.u32.u64 %0, t; }" : "=r"(a) : "l"(p));
    return a;
}

__device__ __forceinline__ float to_tf32(float x) {
    uint32_t u;
    asm("cvt.rna.tf32.f32 %0, %1;" : "=r"(u) : "f"(x));
    return __uint_as_float(u);
}

// ---------------- CSR build ----------------
__global__ void k_zero() {
    int i = blockIdx.x * blockDim.x + threadIdx.x;
    if (i < NN) g_cur[i] = 0;
}

// 4 edges per thread for MLP on the atomic path
__global__ void k_hist(const int* __restrict__ ei) {
    int e0 = (blockIdx.x * blockDim.x + threadIdx.x) * 4;
    #pragma unroll
    for (int j = 0; j < 4; j++) {
        int e = e0 + j;
        if (e < ET) {
            int d = (e < EE) ? ei[EE + e] : (e - EE);
            atomicAdd(&g_cur[d], 1);
        }
    }
}

// single-pass scan: 1024 threads x 20 elements each (20480 >= NN)
__global__ void k_scan() {
    __shared__ int wsum[32];
    int tid = threadIdx.x, lane = tid & 31, wid = tid >> 5;
    int base = tid * 20;
    int v[20];
    int run = 0;
    #pragma unroll
    for (int i = 0; i < 20; i++) {
        int idx = base + i;
        v[i] = (idx < NN) ? g_cur[idx] : 0;
        run += v[i];
    }
    int incl = run;
    #pragma unroll
    for (int o = 1; o < 32; o <<= 1) {
        int t = __shfl_up_sync(0xffffffffu, incl, o);
        if (lane >= o) incl += t;
    }
    if (lane == 31) wsum[wid] = incl;
    __syncthreads();
    if (wid == 0) {
        int s = wsum[lane];
        #pragma unroll
        for (int o = 1; o < 32; o <<= 1) {
            int t = __shfl_up_sync(0xffffffffu, s, o);
            if (lane >= o) s += t;
        }
        wsum[lane] = s;
    }
    __syncthreads();
    int excl = incl - run + (wid ? wsum[wid - 1] : 0);
    #pragma unroll
    for (int i = 0; i < 20; i++) {
        int idx = base + i;
        if (idx < NN) { g_off[idx] = excl; g_cur[idx] = excl; }
        excl += v[i];
    }
    if (tid == 1023) g_off[NN] = wsum[31];
}

__global__ void k_scatter(const int* __restrict__ ei) {
    int e0 = (blockIdx.x * blockDim.x + threadIdx.x) * 4;
    #pragma unroll
    for (int j = 0; j < 4; j++) {
        int e = e0 + j;
        if (e < ET) {
            int s, d;
            if (e < EE) { s = ei[e]; d = ei[EE + e]; }
            else        { s = e - EE; d = s; }
            int pos = atomicAdd(&g_cur[d], 1);
            g_srcs[pos] = s;
        }
    }
}

// ---------------- input rounding ----------------
__global__ __launch_bounds__(256) void k_cvt_x(const float* __restrict__ x) {
    int i4 = blockIdx.x * blockDim.x + threadIdx.x;
    if (i4 >= NN * DD / 4) return;
    float4 v = *(const float4*)(x + i4 * 4);
    v.x = to_tf32(v.x); v.y = to_tf32(v.y); v.z = to_tf32(v.z); v.w = to_tf32(v.w);
    *(float4*)(g_h + i4 * 4) = v;
}

// coalesced transpose + tf32 round: grid (8, 8, nz); matrix = zbase + blockIdx.z
__global__ void k_wcvt_t(
    const float* __restrict__ w0, const float* __restrict__ w1,
    const float* __restrict__ w2, const float* __restrict__ w3,
    const float* __restrict__ w4, const float* __restrict__ w5,
    const float* __restrict__ w6, const float* __restrict__ w7, int zbase) {
    __shared__ float t[32][33];
    int mat = zbase + blockIdx.z;
    const float* W;
    switch (mat) {
        case 0: W = w0; break; case 1: W = w1; break;
        case 2: W = w2; break; case 3: W = w3; break;
        case 4: W = w4; break; case 5: W = w5; break;
        case 6: W = w6; break; default: W = w7; break;
    }
    int kt = blockIdx.x * 32, nt = blockIdx.y * 32;
    int tx = threadIdx.x, ty = threadIdx.y;
    #pragma unroll
    for (int j = 0; j < 4; j++)
        t[ty + j * 8][tx] = W[(kt + ty + j * 8) * DD + nt + tx];
    __syncthreads();
    int mb = mat * (DD * DD);
    #pragma unroll
    for (int j = 0; j < 4; j++)
        g_wt[mb + (nt + ty + j * 8) * DD + kt + tx] = to_tf32(t[tx][ty + j * 8]);
}

// ---------------- TF32 HMMA GEMM: O[20000,256] = A @ W ----------------
#define LDM4(r0, r1, r2, r3, addr) \
    asm volatile("ldmatrix.sync.aligned.m8n8.x4.shared.b16 {%0,%1,%2,%3}, [%4];" \
        : "=r"(r0), "=r"(r1), "=r"(r2), "=r"(r3) : "r"(addr))

__device__ __forceinline__ void mma_tf32(float* d, const uint32_t* a, const uint32_t* b) {
    asm volatile(
        "mma.sync.aligned.m16n8k8.row.col.f32.tf32.tf32.f32 "
        "{%0,%1,%2,%3}, {%4,%5,%6,%7}, {%8,%9}, {%0,%1,%2,%3};"
        : "+f"(d[0]), "+f"(d[1]), "+f"(d[2]), "+f"(d[3])
        : "r"(a[0]), "r"(a[1]), "r"(a[2]), "r"(a[3]), "r"(b[0]), "r"(b[1]));
}

#define CPA(dst, src, sz) \
    asm volatile("cp.async.cg.shared.global [%0], [%1], 16, %2;" \
        :: "r"(dst), "l"(src), "r"(sz) : "memory")
#define CPA_COMMIT() asm volatile("cp.async.commit_group;" ::: "memory")
#define CPA_WAIT(n)  asm volatile("cp.async.wait_group %0;" :: "n"(n) : "memory")

// per-stage: A 64 rows x 64k fp32 (two 128B-row subtiles) + B 128 rows x 64k fp32
#define SMM_A   0                      // 2 subtiles x 8192
#define SMM_B   16384                  // 2 subtiles x 16384
#define STG_SZ  49152
#define SMM_SZ  (2 * STG_SZ)           // 98304 -> 2 CTAs/SM

// grid (314, 2, 2): x = m-tile (64 rows), y = n-half (n0 = y*128), z = which {Wl,Wr}
__global__ __launch_bounds__(128, 2) void k_mm(int lay) {
    extern __shared__ __align__(1024) char sm[];
    uint32_t sb = smem_u32(sm);
    const int tid = threadIdx.x, wid = tid >> 5, lane = tid & 31;
    const int m0 = blockIdx.x * 64;
    const int n0 = blockIdx.y * 128;
    const int which = blockIdx.z;
    const float* __restrict__ Bw = g_wt + (lay * 2 + which) * (DD * DD);
    float* O = which ? g_xr : g_xl;

    const int wm = (wid >> 1) * 32;     // 0,32
    const int wn = (wid & 1) * 64;      // 0,64

    auto issue = [&](int c, int stg) {
        const int k0 = c * 64;
        const uint32_t base = sb + stg * STG_SZ;
        #pragma unroll
        for (int i = 0; i < 8; i++) {
            int idx = tid + i * 128;          // 0..1023
            int sub = idx >> 9, rem = idx & 511;
            int r = rem >> 3, s = rem & 7;    // row 0..63, seg 0..7
            uint32_t b = (uint32_t)(r * 128 + s * 16);
            uint32_t sw = (uint32_t)(sub * 8192) + (b ^ ((b >> 3) & 0x70));
            int m = m0 + r;
            uint32_t sz = (m < NN) ? 16u : 0u;
            int mc = (m < NN) ? m : (NN - 1);
            CPA(base + SMM_A + sw, g_h + mc * DD + k0 + sub * 32 + s * 4, sz);
        }
        #pragma unroll
        for (int i = 0; i < 16; i++) {
            int idx = tid + i * 128;          // 0..2047
            int sub = idx >> 10, rem = idx & 1023;
            int r = rem >> 3, s = rem & 7;    // row 0..127
            uint32_t b = (uint32_t)(r * 128 + s * 16);
            uint32_t sw = (uint32_t)(sub * 16384) + (b ^ ((b >> 3) & 0x70));
            CPA(base + SMM_B + sw, Bw + (n0 + r) * DD + k0 + sub * 32 + s * 4, 16u);
        }
        CPA_COMMIT();
    };

    float acc[2][8][4];
    #pragma unroll
    for (int i = 0; i < 2; i++)
        #pragma unroll
        for (int j = 0; j < 8; j++)
            #pragma unroll
            for (int t = 0; t < 4; t++) acc[i][j][t] = 0.f;

    const int a_row = wm + (lane & 15);                 // 0..47
    const uint32_t a_xr = (uint32_t)((a_row & 7) << 4);
    const uint32_t a_rb = (uint32_t)(a_row * 128);
    const uint32_t s16 = (uint32_t)((lane >> 4) * 16);

    issue(0, 0);
    issue(1, 1);

    #pragma unroll
    for (int c = 0; c < 4; c++) {
        if (c < 3) { CPA_WAIT(1); } else { CPA_WAIT(0); }
        __syncthreads();
        const uint32_t stb = sb + (c & 1) * STG_SZ;

        #pragma unroll
        for (int sub = 0; sub < 2; sub++) {
            const uint32_t abase = stb + SMM_A + sub * 8192;
            const uint32_t bbase = stb + SMM_B + sub * 16384;
            #pragma unroll
            for (int ks = 0; ks < 4; ks++) {
                // b16 view: one tf32 k8-group = 32 bytes (same geometry as bf16 k16)
                const uint32_t col = (uint32_t)(ks * 32) + s16;
                const uint32_t aoff = a_rb + (col ^ a_xr);
                uint32_t a[2][4];
                LDM4(a[0][0], a[0][1], a[0][2], a[0][3], abase + aoff);
                LDM4(a[1][0], a[1][1], a[1][2], a[1][3], abase + aoff + 16 * 128);

                uint32_t bf[8][2];
                #pragma unroll
                for (int p = 0; p < 4; p++) {
                    int br = wn + p * 16 + (lane & 15);
                    uint32_t bo = (uint32_t)(br * 128) + (col ^ ((uint32_t)((br & 7) << 4)));
                    uint32_t r0, r1, r2, r3;
                    LDM4(r0, r1, r2, r3, bbase + bo);
                    bf[2 * p][0] = r0; bf[2 * p + 1][0] = r1;
                    bf[2 * p][1] = r2; bf[2 * p + 1][1] = r3;
                }
                #pragma unroll
                for (int mt = 0; mt < 2; mt++)
                    #pragma unroll
                    for (int nt = 0; nt < 8; nt++)
                        mma_tf32(acc[mt][nt], a[mt], bf[nt]);
            }
        }
        __syncthreads();
        if (c + 2 < 4) issue(c + 2, c & 1);
    }

    // ---- epilogue ----
    const int r_base = m0 + wm + (lane >> 2);
    const int c_base = n0 + wn + (lane & 3) * 2;
    #pragma unroll
    for (int mt = 0; mt < 2; mt++) {
        #pragma unroll
        for (int nt = 0; nt < 8; nt++) {
            int r = r_base + mt * 16;
            int cc = c_base + nt * 8;
            if (r < NN)
                *(float2*)(O + r * DD + cc) = make_float2(acc[mt][nt][0], acc[mt][nt][1]);
            if (r + 8 < NN)
                *(float2*)(O + (r + 8) * DD + cc) = make_float2(acc[mt][nt][2], acc[mt][nt][3]);
        }
    }
}

// ------- fused attention + bias + LayerNorm + ReLU (tf32-rounded h output) -------
__global__ __launch_bounds__(256) void k_attn(const float* __restrict__ att,
                                              const float* __restrict__ bias,
                                              const float* __restrict__ gam,
                                              const float* __restrict__ bet,
                                              float* __restrict__ oext, int to_ext) {
    int gw = (blockIdx.x * blockDim.x + threadIdx.x) >> 5;
    int lane = threadIdx.x & 31;
    if (gw >= NN) return;
    int d = gw;
    int co = lane * 8;

    float xr8[8], at8[8];
    {
        float4 t0 = *(const float4*)(g_xr + d * DD + co);
        float4 t1 = *(const float4*)(g_xr + d * DD + co + 4);
        xr8[0]=t0.x; xr8[1]=t0.y; xr8[2]=t0.z; xr8[3]=t0.w;
        xr8[4]=t1.x; xr8[5]=t1.y; xr8[6]=t1.z; xr8[7]=t1.w;
        float4 u0 = *(const float4*)(att + co);
        float4 u1 = *(const float4*)(att + co + 4);
        at8[0]=u0.x; at8[1]=u0.y; at8[2]=u0.z; at8[3]=u0.w;
        at8[4]=u1.x; at8[5]=u1.y; at8[6]=u1.z; at8[7]=u1.w;
    }

    float M = -3.4e38f, S = 0.f;
    float acc[8];
    #pragma unroll
    for (int j = 0; j < 8; j++) acc[j] = 0.f;

    int p1 = g_off[d + 1];
    for (int p = g_off[d]; p < p1; p++) {
        int s = g_srcs[p];
        float4 a0 = *(const float4*)(g_xl + s * DD + co);
        float4 a1 = *(const float4*)(g_xl + s * DD + co + 4);
        float xl8[8] = {a0.x, a0.y, a0.z, a0.w, a1.x, a1.y, a1.z, a1.w};
        float part = 0.f;
        #pragma unroll
        for (int j = 0; j < 8; j++) {
            float m = xl8[j] + xr8[j];
            m = (m > 0.f) ? m : 0.2f * m;
            part += m * at8[j];
        }
        part += __shfl_xor_sync(0xffffffffu, part, 1);
        part += __shfl_xor_sync(0xffffffffu, part, 2);
        part += __shfl_xor_sync(0xffffffffu, part, 4);
        float Mn = fmaxf(M, part);
        float corr = __expf(M - Mn);
        float w = __expf(part - Mn);
        S = S * corr + w;
        #pragma unroll
        for (int j = 0; j < 8; j++) acc[j] = acc[j] * corr + w * xl8[j];
        M = Mn;
    }
    float inv = 1.f / S;

    float v[8];
    {
        float4 b0 = *(const float4*)(bias + co);
        float4 b1 = *(const float4*)(bias + co + 4);
        v[0]=acc[0]*inv+b0.x; v[1]=acc[1]*inv+b0.y; v[2]=acc[2]*inv+b0.z; v[3]=acc[3]*inv+b0.w;
        v[4]=acc[4]*inv+b1.x; v[5]=acc[5]*inv+b1.y; v[6]=acc[6]*inv+b1.z; v[7]=acc[7]*inv+b1.w;
    }
    float s = 0.f;
    #pragma unroll
    for (int j = 0; j < 8; j++) s += v[j];
    #pragma unroll
    for (int o = 16; o >= 1; o >>= 1) s += __shfl_xor_sync(0xffffffffu, s, o);
    float mu = s * 0.00390625f;
    float q = 0.f;
    #pragma unroll
    for (int j = 0; j < 8; j++) { float t = v[j] - mu; q += t * t; }
    #pragma unroll
    for (int o = 16; o >= 1; o >>= 1) q += __shfl_xor_sync(0xffffffffu, q, o);
    float rr = rsqrtf(q * 0.00390625f + 1e-5f);

    float4 g0 = *(const float4*)(gam + co);
    float4 g1 = *(const float4*)(gam + co + 4);
    float4 e0 = *(const float4*)(bet + co);
    float4 e1 = *(const float4*)(bet + co + 4);
    float y[8];
    y[0] = (v[0]-mu)*rr*g0.x + e0.x; y[1] = (v[1]-mu)*rr*g0.y + e0.y;
    y[2] = (v[2]-mu)*rr*g0.z + e0.z; y[3] = (v[3]-mu)*rr*g0.w + e0.w;
    y[4] = (v[4]-mu)*rr*g1.x + e1.x; y[5] = (v[5]-mu)*rr*g1.y + e1.y;
    y[6] = (v[6]-mu)*rr*g1.z + e1.z; y[7] = (v[7]-mu)*rr*g1.w + e1.w;
    #pragma unroll
    for (int j = 0; j < 8; j++) y[j] = fmaxf(y[j], 0.f);

    if (to_ext) {
        *(float4*)(oext + d * DD + co)     = make_float4(y[0], y[1], y[2], y[3]);
        *(float4*)(oext + d * DD + co + 4) = make_float4(y[4], y[5], y[6], y[7]);
    } else {
        #pragma unroll
        for (int j = 0; j < 8; j++) y[j] = to_tf32(y[j]);
        *(float4*)(g_h + d * DD + co)     = make_float4(y[0], y[1], y[2], y[3]);
        *(float4*)(g_h + d * DD + co + 4) = make_float4(y[4], y[5], y[6], y[7]);
    }
}

// ---------------- launch ----------------
extern "C" void kernel_launch(void* const* d_in, const int* in_sizes, int n_in,
                              void* d_out, int out_size) {
    const float* x  = (const float*)d_in[0];
    const int*   ei = (const int*)  d_in[1];
    float* out = (float*)d_out;

    static cudaStream_t s2 = nullptr;
    static cudaEvent_t evFork = nullptr, evJoin = nullptr;
    if (!s2) {
        cudaStreamCreateWithFlags(&s2, cudaStreamNonBlocking);
        cudaEventCreateWithFlags(&evFork, cudaEventDisableTiming);
        cudaEventCreateWithFlags(&evJoin, cudaEventDisableTiming);
    }

    cudaFuncSetAttribute(k_mm, cudaFuncAttributeMaxDynamicSharedMemorySize, SMM_SZ);

    const float* W[8] = {
        (const float*)d_in[2],  (const float*)d_in[3],    // Wl1, Wr1
        (const float*)d_in[8],  (const float*)d_in[9],    // Wl2, Wr2
        (const float*)d_in[14], (const float*)d_in[15],   // Wl3, Wr3
        (const float*)d_in[20], (const float*)d_in[21] }; // Wl4, Wr4

    // fork: CSR build + layers1-3 weight convert run concurrently with layer-0 GEMM path
    cudaEventRecord(evFork, 0);
    cudaStreamWaitEvent(s2, evFork, 0);

    k_zero<<<(NN + 255) / 256, 256, 0, s2>>>();
    k_hist<<<(ET / 4 + 255) / 256, 256, 0, s2>>>(ei);
    k_scan<<<1, 1024, 0, s2>>>();
    k_scatter<<<(ET / 4 + 255) / 256, 256, 0, s2>>>(ei);
    k_wcvt_t<<<dim3(8, 8, 6), dim3(32, 8), 0, s2>>>(
        W[0], W[1], W[2], W[3], W[4], W[5], W[6], W[7], 2);
    cudaEventRecord(evJoin, s2);

    // main stream: layer-0 critical path
    k_cvt_x<<<(NN * DD / 4 + 255) / 256, 256>>>(x);
    k_wcvt_t<<<dim3(8, 8, 2), dim3(32, 8)>>>(
        W[0], W[1], W[2], W[3], W[4], W[5], W[6], W[7], 0);
    k_mm<<<dim3(314, 2, 2), 128, SMM_SZ>>>(0);

    // join: attention needs CSR; later k_mm layers need converted weights
    cudaStreamWaitEvent(0, evJoin, 0);

    for (int l = 0; l < 4; l++) {
        const float* att = (const float*)d_in[2 + 6 * l + 2];
        const float* b   = (const float*)d_in[2 + 6 * l + 3];
        const float* g   = (const float*)d_in[2 + 6 * l + 4];
        const float* be  = (const float*)d_in[2 + 6 * l + 5];

        if (l > 0) k_mm<<<dim3(314, 2, 2), 128, SMM_SZ>>>(l);
        k_attn<<<2500, 256>>>(att, b, g, be, out, (l == 3) ? 1 : 0);
    }
}

// round 17
// speedup vs baseline: 1.4623x; 1.4623x over previous
#include <cuda_runtime.h>
#include <cuda_fp16.h>
#include <cstdint>

#define NN 20000
#define DD 256
#define EE 320000
#define ET 340000   // EE + NN self loops

// ---------------- device scratch (no allocations allowed) ----------------
__device__ __half g_xlh[NN * DD];       // xl in fp16 (attention gather operand)
__device__ float  g_xr[NN * DD];
__device__ float  g_h[NN * DD];         // activations (tf32-rounded fp32)
__device__ float  g_wt[8 * DD * DD];    // W^T tf32-rounded, [layer*2+which][n][k]
__device__ int    g_off[NN + 1];
__device__ int    g_cur[NN];
__device__ int    g_srcs[ET];

__device__ __forceinline__ uint32_t smem_u32(const void* p) {
    uint32_t a;
    asm("{ .reg .u64 t; cvta.to.shared.u64 t, %1; cvt.u32.u64 %0, t; }" : "=r"(a) : "l"(p));
    return a;
}

__device__ __forceinline__ float to_tf32(float x) {
    uint32_t u;
    asm("cvt.rna.tf32.f32 %0, %1;" : "=r"(u) : "f"(x));
    return __uint_as_float(u);
}

// ---------------- CSR build ----------------
__global__ void k_zero() {
    int i = blockIdx.x * blockDim.x + threadIdx.x;
    if (i < NN) g_cur[i] = 0;
}

__global__ void k_hist(const int* __restrict__ ei) {
    int e = blockIdx.x * blockDim.x + threadIdx.x;
    if (e < ET) {
        int d = (e < EE) ? ei[EE + e] : (e - EE);
        atomicAdd(&g_cur[d], 1);
    }
}

// single-pass scan: 1024 threads x 20 elements each (20480 >= NN)
__global__ void k_scan() {
    __shared__ int wsum[32];
    int tid = threadIdx.x, lane = tid & 31, wid = tid >> 5;
    int base = tid * 20;
    int v[20];
    int run = 0;
    #pragma unroll
    for (int i = 0; i < 20; i++) {
        int idx = base + i;
        v[i] = (idx < NN) ? g_cur[idx] : 0;
        run += v[i];
    }
    int incl = run;
    #pragma unroll
    for (int o = 1; o < 32; o <<= 1) {
        int t = __shfl_up_sync(0xffffffffu, incl, o);
        if (lane >= o) incl += t;
    }
    if (lane == 31) wsum[wid] = incl;
    __syncthreads();
    if (wid == 0) {
        int s = wsum[lane];
        #pragma unroll
        for (int o = 1; o < 32; o <<= 1) {
            int t = __shfl_up_sync(0xffffffffu, s, o);
            if (lane >= o) s += t;
        }
        wsum[lane] = s;
    }
    __syncthreads();
    int excl = incl - run + (wid ? wsum[wid - 1] : 0);
    #pragma unroll
    for (int i = 0; i < 20; i++) {
        int idx = base + i;
        if (idx < NN) { g_off[idx] = excl; g_cur[idx] = excl; }
        excl += v[i];
    }
    if (tid == 1023) g_off[NN] = wsum[31];
}

__global__ void k_scatter(const int* __restrict__ ei) {
    int e = blockIdx.x * blockDim.x + threadIdx.x;
    if (e < ET) {
        int s, d;
        if (e < EE) { s = ei[e]; d = ei[EE + e]; }
        else        { s = e - EE; d = s; }
        int pos = atomicAdd(&g_cur[d], 1);
        g_srcs[pos] = s;
    }
}

// ---------------- input rounding ----------------
__global__ __launch_bounds__(256) void k_cvt_x(const float* __restrict__ x) {
    int i4 = blockIdx.x * blockDim.x + threadIdx.x;
    if (i4 >= NN * DD / 4) return;
    float4 v = *(const float4*)(x + i4 * 4);
    v.x = to_tf32(v.x); v.y = to_tf32(v.y); v.z = to_tf32(v.z); v.w = to_tf32(v.w);
    *(float4*)(g_h + i4 * 4) = v;
}

// coalesced transpose + tf32 round: grid (8, 8, 8) = (k-tile, n-tile, matrix); block (32, 8)
__global__ void k_wcvt_t(
    const float* __restrict__ w0, const float* __restrict__ w1,
    const float* __restrict__ w2, const float* __restrict__ w3,
    const float* __restrict__ w4, const float* __restrict__ w5,
    const float* __restrict__ w6, const float* __restrict__ w7) {
    __shared__ float t[32][33];
    const float* W;
    switch (blockIdx.z) {
        case 0: W = w0; break; case 1: W = w1; break;
        case 2: W = w2; break; case 3: W = w3; break;
        case 4: W = w4; break; case 5: W = w5; break;
        case 6: W = w6; break; default: W = w7; break;
    }
    int kt = blockIdx.x * 32, nt = blockIdx.y * 32;
    int tx = threadIdx.x, ty = threadIdx.y;
    #pragma unroll
    for (int j = 0; j < 4; j++)
        t[ty + j * 8][tx] = W[(kt + ty + j * 8) * DD + nt + tx];
    __syncthreads();
    int mb = blockIdx.z * (DD * DD);
    #pragma unroll
    for (int j = 0; j < 4; j++)
        g_wt[mb + (nt + ty + j * 8) * DD + kt + tx] = to_tf32(t[tx][ty + j * 8]);
}

// ---------------- TF32 HMMA GEMM: O[20000,256] = A @ W ----------------
#define LDM4(r0, r1, r2, r3, addr) \
    asm volatile("ldmatrix.sync.aligned.m8n8.x4.shared.b16 {%0,%1,%2,%3}, [%4];" \
        : "=r"(r0), "=r"(r1), "=r"(r2), "=r"(r3) : "r"(addr))

__device__ __forceinline__ void mma_tf32(float* d, const uint32_t* a, const uint32_t* b) {
    asm volatile(
        "mma.sync.aligned.m16n8k8.row.col.f32.tf32.tf32.f32 "
        "{%0,%1,%2,%3}, {%4,%5,%6,%7}, {%8,%9}, {%0,%1,%2,%3};"
        : "+f"(d[0]), "+f"(d[1]), "+f"(d[2]), "+f"(d[3])
        : "r"(a[0]), "r"(a[1]), "r"(a[2]), "r"(a[3]), "r"(b[0]), "r"(b[1]));
}

#define CPA(dst, src, sz) \
    asm volatile("cp.async.cg.shared.global [%0], [%1], 16, %2;" \
        :: "r"(dst), "l"(src), "r"(sz) : "memory")
#define CPA_COMMIT() asm volatile("cp.async.commit_group;" ::: "memory")
#define CPA_WAIT(n)  asm volatile("cp.async.wait_group %0;" :: "n"(n) : "memory")

// per-stage: A 64 rows x 64k fp32 (two 128B-row subtiles) + B 128 rows x 64k fp32
#define SMM_A   0                      // 2 subtiles x 8192
#define SMM_B   16384                  // 2 subtiles x 16384
#define STG_SZ  49152
#define SMM_SZ  (2 * STG_SZ)           // 98304 -> 2 CTAs/SM

// grid (314, 2, 2): x = m-tile (64 rows), y = n-half (n0 = y*128), z = which {Wl,Wr}
__global__ __launch_bounds__(128, 2) void k_mm(int lay) {
    extern __shared__ __align__(1024) char sm[];
    uint32_t sb = smem_u32(sm);
    const int tid = threadIdx.x, wid = tid >> 5, lane = tid & 31;
    const int m0 = blockIdx.x * 64;
    const int n0 = blockIdx.y * 128;
    const int which = blockIdx.z;
    const float* __restrict__ Bw = g_wt + (lay * 2 + which) * (DD * DD);

    const int wm = (wid >> 1) * 32;     // 0,32
    const int wn = (wid & 1) * 64;      // 0,64

    auto issue = [&](int c, int stg) {
        const int k0 = c * 64;
        const uint32_t base = sb + stg * STG_SZ;
        #pragma unroll
        for (int i = 0; i < 8; i++) {
            int idx = tid + i * 128;          // 0..1023
            int sub = idx >> 9, rem = idx & 511;
            int r = rem >> 3, s = rem & 7;    // row 0..63, seg 0..7
            uint32_t b = (uint32_t)(r * 128 + s * 16);
            uint32_t sw = (uint32_t)(sub * 8192) + (b ^ ((b >> 3) & 0x70));
            int m = m0 + r;
            uint32_t sz = (m < NN) ? 16u : 0u;
            int mc = (m < NN) ? m : (NN - 1);
            CPA(base + SMM_A + sw, g_h + mc * DD + k0 + sub * 32 + s * 4, sz);
        }
        #pragma unroll
        for (int i = 0; i < 16; i++) {
            int idx = tid + i * 128;          // 0..2047
            int sub = idx >> 10, rem = idx & 1023;
            int r = rem >> 3, s = rem & 7;    // row 0..127
            uint32_t b = (uint32_t)(r * 128 + s * 16);
            uint32_t sw = (uint32_t)(sub * 16384) + (b ^ ((b >> 3) & 0x70));
            CPA(base + SMM_B + sw, Bw + (n0 + r) * DD + k0 + sub * 32 + s * 4, 16u);
        }
        CPA_COMMIT();
    };

    float acc[2][8][4];
    #pragma unroll
    for (int i = 0; i < 2; i++)
        #pragma unroll
        for (int j = 0; j < 8; j++)
            #pragma unroll
            for (int t = 0; t < 4; t++) acc[i][j][t] = 0.f;

    const int a_row = wm + (lane & 15);                 // 0..47
    const uint32_t a_xr = (uint32_t)((a_row & 7) << 4);
    const uint32_t a_rb = (uint32_t)(a_row * 128);
    const uint32_t s16 = (uint32_t)((lane >> 4) * 16);

    issue(0, 0);
    issue(1, 1);

    #pragma unroll
    for (int c = 0; c < 4; c++) {
        if (c < 3) { CPA_WAIT(1); } else { CPA_WAIT(0); }
        __syncthreads();
        const uint32_t stb = sb + (c & 1) * STG_SZ;

        #pragma unroll
        for (int sub = 0; sub < 2; sub++) {
            const uint32_t abase = stb + SMM_A + sub * 8192;
            const uint32_t bbase = stb + SMM_B + sub * 16384;
            #pragma unroll
            for (int ks = 0; ks < 4; ks++) {
                // b16 view: one tf32 k8-group = 32 bytes (same geometry as bf16 k16)
                const uint32_t col = (uint32_t)(ks * 32) + s16;
                const uint32_t aoff = a_rb + (col ^ a_xr);
                uint32_t a[2][4];
                LDM4(a[0][0], a[0][1], a[0][2], a[0][3], abase + aoff);
                LDM4(a[1][0], a[1][1], a[1][2], a[1][3], abase + aoff + 16 * 128);

                uint32_t bf[8][2];
                #pragma unroll
                for (int p = 0; p < 4; p++) {
                    int br = wn + p * 16 + (lane & 15);
                    uint32_t bo = (uint32_t)(br * 128) + (col ^ ((uint32_t)((br & 7) << 4)));
                    uint32_t r0, r1, r2, r3;
                    LDM4(r0, r1, r2, r3, bbase + bo);
                    bf[2 * p][0] = r0; bf[2 * p + 1][0] = r1;
                    bf[2 * p][1] = r2; bf[2 * p + 1][1] = r3;
                }
                #pragma unroll
                for (int mt = 0; mt < 2; mt++)
                    #pragma unroll
                    for (int nt = 0; nt < 8; nt++)
                        mma_tf32(acc[mt][nt], a[mt], bf[nt]);
            }
        }
        __syncthreads();
        if (c + 2 < 4) issue(c + 2, c & 1);
    }

    // ---- epilogue: xl -> fp16, xr -> fp32 ----
    const int r_base = m0 + wm + (lane >> 2);
    const int c_base = n0 + wn + (lane & 3) * 2;
    if (which == 0) {
        #pragma unroll
        for (int mt = 0; mt < 2; mt++) {
            #pragma unroll
            for (int nt = 0; nt < 8; nt++) {
                int r = r_base + mt * 16;
                int cc = c_base + nt * 8;
                if (r < NN)
                    *(__half2*)(g_xlh + r * DD + cc) =
                        __floats2half2_rn(acc[mt][nt][0], acc[mt][nt][1]);
                if (r + 8 < NN)
                    *(__half2*)(g_xlh + (r + 8) * DD + cc) =
                        __floats2half2_rn(acc[mt][nt][2], acc[mt][nt][3]);
            }
        }
    } else {
        #pragma unroll
        for (int mt = 0; mt < 2; mt++) {
            #pragma unroll
            for (int nt = 0; nt < 8; nt++) {
                int r = r_base + mt * 16;
                int cc = c_base + nt * 8;
                if (r < NN)
                    *(float2*)(g_xr + r * DD + cc) = make_float2(acc[mt][nt][0], acc[mt][nt][1]);
                if (r + 8 < NN)
                    *(float2*)(g_xr + (r + 8) * DD + cc) = make_float2(acc[mt][nt][2], acc[mt][nt][3]);
            }
        }
    }
}

// ------- fused attention + bias + LayerNorm + ReLU (tf32-rounded h output) -------
__global__ __launch_bounds__(256) void k_attn(const float* __restrict__ att,
                                              const float* __restrict__ bias,
                                              const float* __restrict__ gam,
                                              const float* __restrict__ bet,
                                              float* __restrict__ oext, int to_ext) {
    int gw = (blockIdx.x * blockDim.x + threadIdx.x) >> 5;
    int lane = threadIdx.x & 31;
    if (gw >= NN) return;
    int d = gw;
    int co = lane * 8;

    float xr8[8], at8[8];
    {
        float4 t0 = *(const float4*)(g_xr + d * DD + co);
        float4 t1 = *(const float4*)(g_xr + d * DD + co + 4);
        xr8[0]=t0.x; xr8[1]=t0.y; xr8[2]=t0.z; xr8[3]=t0.w;
        xr8[4]=t1.x; xr8[5]=t1.y; xr8[6]=t1.z; xr8[7]=t1.w;
        float4 u0 = *(const float4*)(att + co);
        float4 u1 = *(const float4*)(att + co + 4);
        at8[0]=u0.x; at8[1]=u0.y; at8[2]=u0.z; at8[3]=u0.w;
        at8[4]=u1.x; at8[5]=u1.y; at8[6]=u1.z; at8[7]=u1.w;
    }

    float M = -3.4e38f, S = 0.f;
    float acc[8];
    #pragma unroll
    for (int j = 0; j < 8; j++) acc[j] = 0.f;

    int p1 = g_off[d + 1];
    for (int p = g_off[d]; p < p1; p++) {
        int s = g_srcs[p];
        // 8 fp16 channels = 16 bytes per lane
        uint4 raw = *(const uint4*)(g_xlh + s * DD + co);
        float2 c0 = __half22float2(*(__half2*)&raw.x);
        float2 c1 = __half22float2(*(__half2*)&raw.y);
        float2 c2 = __half22float2(*(__half2*)&raw.z);
        float2 c3 = __half22float2(*(__half2*)&raw.w);
        float xl8[8] = {c0.x, c0.y, c1.x, c1.y, c2.x, c2.y, c3.x, c3.y};
        float part = 0.f;
        #pragma unroll
        for (int j = 0; j < 8; j++) {
            float m = xl8[j] + xr8[j];
            m = (m > 0.f) ? m : 0.2f * m;
            part += m * at8[j];
        }
        part += __shfl_xor_sync(0xffffffffu, part, 1);
        part += __shfl_xor_sync(0xffffffffu, part, 2);
        part += __shfl_xor_sync(0xffffffffu, part, 4);
        float Mn = fmaxf(M, part);
        float corr = __expf(M - Mn);
        float w = __expf(part - Mn);
        S = S * corr + w;
        #pragma unroll
        for (int j = 0; j < 8; j++) acc[j] = acc[j] * corr + w * xl8[j];
        M = Mn;
    }
    float inv = 1.f / S;

    float v[8];
    {
        float4 b0 = *(const float4*)(bias + co);
        float4 b1 = *(const float4*)(bias + co + 4);
        v[0]=acc[0]*inv+b0.x; v[1]=acc[1]*inv+b0.y; v[2]=acc[2]*inv+b0.z; v[3]=acc[3]*inv+b0.w;
        v[4]=acc[4]*inv+b1.x; v[5]=acc[5]*inv+b1.y; v[6]=acc[6]*inv+b1.z; v[7]=acc[7]*inv+b1.w;
    }
    float s = 0.f;
    #pragma unroll
    for (int j = 0; j < 8; j++) s += v[j];
    #pragma unroll
    for (int o = 16; o >= 1; o >>= 1) s += __shfl_xor_sync(0xffffffffu, s, o);
    float mu = s * 0.00390625f;
    float q = 0.f;
    #pragma unroll
    for (int j = 0; j < 8; j++) { float t = v[j] - mu; q += t * t; }
    #pragma unroll
    for (int o = 16; o >= 1; o >>= 1) q += __shfl_xor_sync(0xffffffffu, q, o);
    float rr = rsqrtf(q * 0.00390625f + 1e-5f);

    float4 g0 = *(const float4*)(gam + co);
    float4 g1 = *(const float4*)(gam + co + 4);
    float4 e0 = *(const float4*)(bet + co);
    float4 e1 = *(const float4*)(bet + co + 4);
    float y[8];
    y[0] = (v[0]-mu)*rr*g0.x + e0.x; y[1] = (v[1]-mu)*rr*g0.y + e0.y;
    y[2] = (v[2]-mu)*rr*g0.z + e0.z; y[3] = (v[3]-mu)*rr*g0.w + e0.w;
    y[4] = (v[4]-mu)*rr*g1.x + e1.x; y[5] = (v[5]-mu)*rr*g1.y + e1.y;
    y[6] = (v[6]-mu)*rr*g1.z + e1.z; y[7] = (v[7]-mu)*rr*g1.w + e1.w;
    #pragma unroll
    for (int j = 0; j < 8; j++) y[j] = fmaxf(y[j], 0.f);

    if (to_ext) {
        *(float4*)(oext + d * DD + co)     = make_float4(y[0], y[1], y[2], y[3]);
        *(float4*)(oext + d * DD + co + 4) = make_float4(y[4], y[5], y[6], y[7]);
    } else {
        #pragma unroll
        for (int j = 0; j < 8; j++) y[j] = to_tf32(y[j]);
        *(float4*)(g_h + d * DD + co)     = make_float4(y[0], y[1], y[2], y[3]);
        *(float4*)(g_h + d * DD + co + 4) = make_float4(y[4], y[5], y[6], y[7]);
    }
}

// ---------------- launch ----------------
extern "C" void kernel_launch(void* const* d_in, const int* in_sizes, int n_in,
                              void* d_out, int out_size) {
    const float* x  = (const float*)d_in[0];
    const int*   ei = (const int*)  d_in[1];
    float* out = (float*)d_out;

    cudaFuncSetAttribute(k_mm, cudaFuncAttributeMaxDynamicSharedMemorySize, SMM_SZ);

    // CSR build (single stream — fork experiment regressed, reverted)
    k_zero<<<(NN + 255) / 256, 256>>>();
    k_hist<<<(ET + 255) / 256, 256>>>(ei);
    k_scan<<<1, 1024>>>();
    k_scatter<<<(ET + 255) / 256, 256>>>(ei);

    // layer-0 input -> tf32-rounded fp32
    k_cvt_x<<<(NN * DD / 4 + 255) / 256, 256>>>(x);

    // all 8 weight matrices -> transposed tf32-rounded fp32
    k_wcvt_t<<<dim3(8, 8, 8), dim3(32, 8)>>>(
        (const float*)d_in[2],  (const float*)d_in[3],    // Wl1, Wr1
        (const float*)d_in[8],  (const float*)d_in[9],    // Wl2, Wr2
        (const float*)d_in[14], (const float*)d_in[15],   // Wl3, Wr3
        (const float*)d_in[20], (const float*)d_in[21]);  // Wl4, Wr4

    for (int l = 0; l < 4; l++) {
        const float* att = (const float*)d_in[2 + 6 * l + 2];
        const float* b   = (const float*)d_in[2 + 6 * l + 3];
        const float* g   = (const float*)d_in[2 + 6 * l + 4];
        const float* be  = (const float*)d_in[2 + 6 * l + 5];

        k_mm<<<dim3(314, 2, 2), 128, SMM_SZ>>>(l);
        k_attn<<<2500, 256>>>(att, b, g, be, out, (l == 3) ? 1 : 0);
    }
}